// round 5
// baseline (speedup 1.0000x reference)
#include <cuda_runtime.h>
#include <cuda_fp16.h>
#include <cuda_bf16.h>
#include <math.h>

// Problem dims
#define BB 64
#define NN 512
#define DD 256
#define HH 512
#define MAX_ITER 20
#define NTILE 16               // pooling tiles per batch (32 rows each)

#define ZM (BB * NN)           // 32768

// Scratch (allocation-free: __device__ globals)
__device__ __half g_Z[(size_t)ZM * HH];        // 32 MiB: Z = V@W1v + b1 (fp16)
__device__ __half g_VH[(size_t)ZM * DD];       // 16 MiB: fp16 copy of V (pooling only)
__device__ float  g_q[BB * NN];                // scratch q (dead stores mid-loop)
__device__ float  g_u[BB * HH];
__device__ float  g_part[BB * NTILE * DD];     // 1 MiB pooling partials

__device__ __forceinline__ unsigned f2tf32(float x) {
    unsigned r;
    asm("cvt.rna.tf32.f32 %0, %1;" : "=r"(r) : "f"(x));
    return r;
}

#define CP_ASYNC16(dst, src) \
    asm volatile("cp.async.cg.shared.global [%0], [%1], 16;\n" :: "r"(dst), "l"(src))
#define CP_COMMIT() asm volatile("cp.async.commit_group;\n" ::)
#define CP_WAIT(n)  asm volatile("cp.async.wait_group %0;\n" :: "n"(n))

// ---------------------------------------------------------------------------
// Kernel 0 (once): VH = half(V)
// ---------------------------------------------------------------------------
__global__ __launch_bounds__(256) void convert_v_kernel(const float* __restrict__ V)
{
    // 8388608 elems / (4096 CTAs * 256 thr) = 8 elems per thread
    size_t i = ((size_t)blockIdx.x * 256 + threadIdx.x) * 8;
    const float4* src = (const float4*)(V + i);
    float4 a = src[0], b = src[1];
    uint4 o;
    *(__half2*)&o.x = __floats2half2_rn(a.x, a.y);
    *(__half2*)&o.y = __floats2half2_rn(a.z, a.w);
    *(__half2*)&o.z = __floats2half2_rn(b.x, b.y);
    *(__half2*)&o.w = __floats2half2_rn(b.z, b.w);
    *(uint4*)(g_VH + i) = o;
}

// ---------------------------------------------------------------------------
// Kernel 1 (once): Z = V @ W1v + b1  (M=32768, K=256, N=512), TF32 mma.sync
// CTA tile 128x128, BK=16, cp.async double-buffered, fp16 epilogue.
// ---------------------------------------------------------------------------
#define BK 16
#define APAD 20
#define BPAD 136

__global__ __launch_bounds__(256) void zgemm_kernel(
    const float* __restrict__ V,
    const float* __restrict__ W1,
    const float* __restrict__ b1)
{
    __shared__ float As[2][128][APAD];
    __shared__ float Bs[2][BK][BPAD];

    const int tid   = threadIdx.x;
    const int warp  = tid >> 5;
    const int lane  = tid & 31;
    const int g     = lane >> 2;
    const int tg    = lane & 3;
    const int warpM = warp >> 1;
    const int warpN = warp & 1;

    const int blockN = blockIdx.x;   // 0..3
    const int blockM = blockIdx.y;   // 0..255

    const float* Abase = V + (size_t)blockM * 128 * DD;
    const float* Bbase = W1 + blockN * 128;

    float c[2][8][4];
    #pragma unroll
    for (int mt = 0; mt < 2; mt++)
        #pragma unroll
        for (int nt = 0; nt < 8; nt++)
            #pragma unroll
            for (int i = 0; i < 4; i++) c[mt][nt][i] = 0.f;

    unsigned sA = (unsigned)__cvta_generic_to_shared(&As[0][0][0]);
    unsigned sB = (unsigned)__cvta_generic_to_shared(&Bs[0][0][0]);
    const unsigned stageA = 128 * APAD * 4;
    const unsigned stageB = BK * BPAD * 4;

    auto issue_loads = [&](int k0, int st) {
        #pragma unroll
        for (int t = 0; t < 2; t++) {
            int idx = tid + t * 256;
            int r = idx >> 2, kc = idx & 3;
            CP_ASYNC16(sA + st * stageA + (r * APAD + kc * 4) * 4,
                       Abase + (size_t)r * DD + k0 + kc * 4);
        }
        #pragma unroll
        for (int t = 0; t < 2; t++) {
            int idx = tid + t * 256;
            int r = idx >> 5, cc = idx & 31;
            CP_ASYNC16(sB + st * stageB + (r * BPAD + cc * 4) * 4,
                       Bbase + (size_t)(k0 + r) * HH + cc * 4);
        }
        CP_COMMIT();
    };

    issue_loads(0, 0);

    const int NCHUNK = DD / BK;   // 16
    for (int ch = 0; ch < NCHUNK; ch++) {
        int st = ch & 1;
        if (ch + 1 < NCHUNK) {
            issue_loads((ch + 1) * BK, st ^ 1);
            CP_WAIT(1);
        } else {
            CP_WAIT(0);
        }
        __syncthreads();

        #pragma unroll
        for (int kk = 0; kk < BK; kk += 8) {
            unsigned a[2][4];
            #pragma unroll
            for (int mt = 0; mt < 2; mt++) {
                int ar = warpM * 32 + mt * 16 + g;
                a[mt][0] = f2tf32(As[st][ar][kk + tg]);
                a[mt][1] = f2tf32(As[st][ar + 8][kk + tg]);
                a[mt][2] = f2tf32(As[st][ar][kk + tg + 4]);
                a[mt][3] = f2tf32(As[st][ar + 8][kk + tg + 4]);
            }
            #pragma unroll
            for (int nt = 0; nt < 8; nt++) {
                int bc = warpN * 64 + nt * 8 + g;
                unsigned b0 = f2tf32(Bs[st][kk + tg][bc]);
                unsigned bq = f2tf32(Bs[st][kk + tg + 4][bc]);
                #pragma unroll
                for (int mt = 0; mt < 2; mt++) {
                    asm volatile(
                        "mma.sync.aligned.m16n8k8.row.col.f32.tf32.tf32.f32 "
                        "{%0,%1,%2,%3}, {%4,%5,%6,%7}, {%8,%9}, {%0,%1,%2,%3};"
                        : "+f"(c[mt][nt][0]), "+f"(c[mt][nt][1]),
                          "+f"(c[mt][nt][2]), "+f"(c[mt][nt][3])
                        : "r"(a[mt][0]), "r"(a[mt][1]), "r"(a[mt][2]), "r"(a[mt][3]),
                          "r"(b0), "r"(bq));
                }
            }
        }
        __syncthreads();
    }

    __half2* Z2 = (__half2*)g_Z;
    #pragma unroll
    for (int mt = 0; mt < 2; mt++) {
        int row0 = blockM * 128 + warpM * 32 + mt * 16 + g;
        #pragma unroll
        for (int nt = 0; nt < 8; nt++) {
            int col = blockN * 128 + warpN * 64 + nt * 8 + 2 * tg;
            float bA = b1[col], bBv = b1[col + 1];
            Z2[((size_t)row0 * HH + col) >> 1] =
                __floats2half2_rn(c[mt][nt][0] + bA, c[mt][nt][1] + bBv);
            Z2[((size_t)(row0 + 8) * HH + col) >> 1] =
                __floats2half2_rn(c[mt][nt][2] + bA, c[mt][nt][3] + bBv);
        }
    }
}

// ---------------------------------------------------------------------------
// Pooling partial over one (b, 32-row tile), q provided in smem.
// Writes g_part[(b*NTILE + t) * DD + d].
// 256 threads: lane-of-32 handles 8 d's (uint4 of VH), 8 row-stripes of 4 rows.
// ---------------------------------------------------------------------------
__device__ __forceinline__ void pool_tile(const float* qs /*[32] smem*/,
                                          int b, int t, int tid,
                                          float4* red /*smem [8][64]*/)
{
    const int lane = tid & 31;      // d-chunk: halves lane*8 .. lane*8+7
    const int strp = tid >> 5;      // 0..7 -> rows strp*4 .. strp*4+3
    const int n0   = t * 32;

    float acc[8];
    #pragma unroll
    for (int i = 0; i < 8; i++) acc[i] = 0.f;

    #pragma unroll
    for (int r = 0; r < 4; r++) {
        int n = n0 + strp * 4 + r;
        float qv = qs[strp * 4 + r];
        const uint4 vz = *(const uint4*)(g_VH + (size_t)(b * NN + n) * DD + lane * 8);
        float2 v0 = __half22float2(*(__half2*)&vz.x);
        float2 v1 = __half22float2(*(__half2*)&vz.y);
        float2 v2 = __half22float2(*(__half2*)&vz.z);
        float2 v3 = __half22float2(*(__half2*)&vz.w);
        acc[0] += qv * v0.x; acc[1] += qv * v0.y;
        acc[2] += qv * v1.x; acc[3] += qv * v1.y;
        acc[4] += qv * v2.x; acc[5] += qv * v2.y;
        acc[6] += qv * v3.x; acc[7] += qv * v3.y;
    }
    // stage per-stripe partials: red[strp][lane*2 + j] holds float4 (8 floats/lane)
    red[strp * 64 + lane * 2]     = make_float4(acc[0], acc[1], acc[2], acc[3]);
    red[strp * 64 + lane * 2 + 1] = make_float4(acc[4], acc[5], acc[6], acc[7]);
    __syncthreads();
    // reduce over 8 stripes: thread tid handles d4 = tid (0..63) -> 4 d's
    if (tid < 64) {
        float4 s = red[tid];
        #pragma unroll
        for (int sx = 1; sx < 8; sx++) {
            float4 p = red[sx * 64 + tid];
            s.x += p.x; s.y += p.y; s.z += p.z; s.w += p.w;
        }
        ((float4*)g_part)[(b * NTILE + t) * (DD / 4) + tid] = s;
    }
}

// ---------------------------------------------------------------------------
// Kernel P0 (once): pooling partials from q_init.
// grid (NTILE, BB), 256 threads.
// ---------------------------------------------------------------------------
__global__ __launch_bounds__(256) void pool0_kernel(const float* __restrict__ q)
{
    const int t = blockIdx.x, b = blockIdx.y, tid = threadIdx.x;
    __shared__ float qs[32];
    __shared__ float4 red[8 * 64];
    if (tid < 32) qs[tid] = q[b * NN + t * 32 + tid];
    __syncthreads();
    pool_tile(qs, b, t, tid, red);
}

// ---------------------------------------------------------------------------
// Kernel U (per iter): pooled = sum of partials; u = pooled @ W1p.
// grid (BB, 2), 256 threads.
// ---------------------------------------------------------------------------
__global__ __launch_bounds__(256) void u_kernel(
    const float* __restrict__ W1,
    float* __restrict__ u)
{
    const int b    = blockIdx.x;
    const int half = blockIdx.y;
    const int tid  = threadIdx.x;

    __shared__ float pooled_s[DD];

    float p = 0.f;
    #pragma unroll
    for (int s = 0; s < NTILE; s++)
        p += g_part[(b * NTILE + s) * DD + tid];
    pooled_s[tid] = p;
    __syncthreads();

    const float* __restrict__ W1p = W1 + (size_t)DD * HH;
    const int h = half * 256 + tid;
    float a = 0.f;
    #pragma unroll 8
    for (int d = 0; d < DD; d++)
        a += pooled_s[d] * W1p[(size_t)d * HH + h];
    u[b * HH + h] = a;
}

// ---------------------------------------------------------------------------
// Kernel S (per iter): fused score + pooling partial.
// CTA (b, t): 32 rows. q'[n] = sigmoid(sum_h relu(Z+u)*w2 + b2), then
// pooling partial of q' over VH tile.
// ---------------------------------------------------------------------------
__global__ __launch_bounds__(256) void score_pool_kernel(
    const float* __restrict__ u,    // [B, H]
    const float* __restrict__ W2,   // [H]
    const float* __restrict__ b2,   // [1]
    float* __restrict__ qout)       // [B, N]
{
    const int t   = blockIdx.x;     // 0..15
    const int b   = blockIdx.y;     // 0..63
    const int tid = threadIdx.x;
    const int w   = tid >> 5;
    const int l   = tid & 31;

    __shared__ float4 us4[HH / 4];
    __shared__ float4 w24[HH / 4];
    __shared__ float  qs[32];
    __shared__ float4 red[8 * 64];

    if (tid < HH / 4) {
        us4[tid] = ((const float4*)(u + b * HH))[tid];
        w24[tid] = ((const float4*)W2)[tid];
    }
    __syncthreads();

    const float b2v = b2[0];

    #pragma unroll
    for (int r = 0; r < 4; r++) {
        const int n = t * 32 + w * 4 + r;
        const uint4* __restrict__ z8 =
            (const uint4*)(g_Z + (size_t)(b * NN + n) * HH);
        float acc = 0.f;
        #pragma unroll
        for (int k = 0; k < 2; k++) {
            int idx = l + 32 * k;
            uint4 zr = z8[idx];
            float4 u0 = us4[idx * 2], u1 = us4[idx * 2 + 1];
            float4 w0 = w24[idx * 2], w1 = w24[idx * 2 + 1];
            float2 za = __half22float2(*(__half2*)&zr.x);
            float2 zb = __half22float2(*(__half2*)&zr.y);
            float2 zc = __half22float2(*(__half2*)&zr.z);
            float2 zd = __half22float2(*(__half2*)&zr.w);
            acc += fmaxf(za.x + u0.x, 0.f) * w0.x;
            acc += fmaxf(za.y + u0.y, 0.f) * w0.y;
            acc += fmaxf(zb.x + u0.z, 0.f) * w0.z;
            acc += fmaxf(zb.y + u0.w, 0.f) * w0.w;
            acc += fmaxf(zc.x + u1.x, 0.f) * w1.x;
            acc += fmaxf(zc.y + u1.y, 0.f) * w1.y;
            acc += fmaxf(zd.x + u1.z, 0.f) * w1.z;
            acc += fmaxf(zd.y + u1.w, 0.f) * w1.w;
        }
        #pragma unroll
        for (int off = 16; off; off >>= 1)
            acc += __shfl_xor_sync(0xffffffffu, acc, off);
        if (l == 0) {
            float qv = 1.f / (1.f + expf(-(acc + b2v)));
            qs[w * 4 + r] = qv;
            qout[b * NN + n] = qv;
        }
    }
    __syncthreads();

    // fused pooling partial using freshly computed q'
    pool_tile(qs, b, t, tid, red);
}

// ---------------------------------------------------------------------------
extern "C" void kernel_launch(void* const* d_in, const int* in_sizes, int n_in,
                              void* d_out, int out_size) {
    const float* q_init = (const float*)d_in[0];
    const float* V      = (const float*)d_in[1];
    const float* W1     = (const float*)d_in[2];
    const float* b1     = (const float*)d_in[3];
    const float* W2     = (const float*)d_in[4];
    const float* b2     = (const float*)d_in[5];
    float* out = (float*)d_out;

    float* g_q_p;
    float* g_u_p;
    cudaGetSymbolAddress((void**)&g_q_p, g_q);
    cudaGetSymbolAddress((void**)&g_u_p, g_u);

    convert_v_kernel<<<4096, 256>>>(V);
    zgemm_kernel<<<dim3(4, 256), 256>>>(V, W1, b1);
    pool0_kernel<<<dim3(NTILE, BB), 256>>>(q_init);

    for (int it = 0; it < MAX_ITER; it++) {
        u_kernel<<<dim3(BB, 2), 256>>>(W1, g_u_p);
        float* qdst = (it == MAX_ITER - 1) ? out : g_q_p;
        score_pool_kernel<<<dim3(NTILE, BB), 256>>>(g_u_p, W2, b2, qdst);
    }
}

// round 6
// speedup vs baseline: 1.3130x; 1.3130x over previous
#include <cuda_runtime.h>
#include <cuda_fp16.h>
#include <cuda_bf16.h>
#include <math.h>

// Problem dims
#define BB 64
#define NN 512
#define DD 256
#define HH 512
#define MAX_ITER 20
#define NTILE 16               // pooling tiles per batch (32 rows each)

#define ZM (BB * NN)           // 32768

// Scratch (allocation-free: __device__ globals)
__device__ __half g_Z[(size_t)ZM * HH];        // 32 MiB: Z = V@W1v + b1 (fp16)
__device__ __half g_VH[(size_t)ZM * DD];       // 16 MiB: fp16 copy of V (pooling only)
__device__ float  g_q[BB * NN];                // scratch q
__device__ float  g_u[BB * HH];
__device__ float  g_part[BB * NTILE * DD];     // 1 MiB pooling partials

__device__ __forceinline__ unsigned f2tf32(float x) {
    unsigned r;
    asm("cvt.rna.tf32.f32 %0, %1;" : "=r"(r) : "f"(x));
    return r;
}

#define CP_ASYNC16(dst, src) \
    asm volatile("cp.async.cg.shared.global [%0], [%1], 16;\n" :: "r"(dst), "l"(src))
#define CP_COMMIT() asm volatile("cp.async.commit_group;\n" ::)
#define CP_WAIT(n)  asm volatile("cp.async.wait_group %0;\n" :: "n"(n))

// ---------------------------------------------------------------------------
// Kernel 0 (once): VH = half(V)
// ---------------------------------------------------------------------------
__global__ __launch_bounds__(256) void convert_v_kernel(const float* __restrict__ V)
{
    size_t i = ((size_t)blockIdx.x * 256 + threadIdx.x) * 8;
    const float4* src = (const float4*)(V + i);
    float4 a = src[0], b = src[1];
    uint4 o;
    *(__half2*)&o.x = __floats2half2_rn(a.x, a.y);
    *(__half2*)&o.y = __floats2half2_rn(a.z, a.w);
    *(__half2*)&o.z = __floats2half2_rn(b.x, b.y);
    *(__half2*)&o.w = __floats2half2_rn(b.z, b.w);
    *(uint4*)(g_VH + i) = o;
}

// ---------------------------------------------------------------------------
// Kernel 1 (once): Z = V @ W1v + b1  (TF32 mma.sync, cp.async double-buffered)
// ---------------------------------------------------------------------------
#define BK 16
#define APAD 20
#define BPAD 136

__global__ __launch_bounds__(256) void zgemm_kernel(
    const float* __restrict__ V,
    const float* __restrict__ W1,
    const float* __restrict__ b1)
{
    __shared__ float As[2][128][APAD];
    __shared__ float Bs[2][BK][BPAD];

    const int tid   = threadIdx.x;
    const int warp  = tid >> 5;
    const int lane  = tid & 31;
    const int g     = lane >> 2;
    const int tg    = lane & 3;
    const int warpM = warp >> 1;
    const int warpN = warp & 1;

    const int blockN = blockIdx.x;   // 0..3
    const int blockM = blockIdx.y;   // 0..255

    const float* Abase = V + (size_t)blockM * 128 * DD;
    const float* Bbase = W1 + blockN * 128;

    float c[2][8][4];
    #pragma unroll
    for (int mt = 0; mt < 2; mt++)
        #pragma unroll
        for (int nt = 0; nt < 8; nt++)
            #pragma unroll
            for (int i = 0; i < 4; i++) c[mt][nt][i] = 0.f;

    unsigned sA = (unsigned)__cvta_generic_to_shared(&As[0][0][0]);
    unsigned sB = (unsigned)__cvta_generic_to_shared(&Bs[0][0][0]);
    const unsigned stageA = 128 * APAD * 4;
    const unsigned stageB = BK * BPAD * 4;

    auto issue_loads = [&](int k0, int st) {
        #pragma unroll
        for (int t = 0; t < 2; t++) {
            int idx = tid + t * 256;
            int r = idx >> 2, kc = idx & 3;
            CP_ASYNC16(sA + st * stageA + (r * APAD + kc * 4) * 4,
                       Abase + (size_t)r * DD + k0 + kc * 4);
        }
        #pragma unroll
        for (int t = 0; t < 2; t++) {
            int idx = tid + t * 256;
            int r = idx >> 5, cc = idx & 31;
            CP_ASYNC16(sB + st * stageB + (r * BPAD + cc * 4) * 4,
                       Bbase + (size_t)(k0 + r) * HH + cc * 4);
        }
        CP_COMMIT();
    };

    issue_loads(0, 0);

    const int NCHUNK = DD / BK;   // 16
    for (int ch = 0; ch < NCHUNK; ch++) {
        int st = ch & 1;
        if (ch + 1 < NCHUNK) {
            issue_loads((ch + 1) * BK, st ^ 1);
            CP_WAIT(1);
        } else {
            CP_WAIT(0);
        }
        __syncthreads();

        #pragma unroll
        for (int kk = 0; kk < BK; kk += 8) {
            unsigned a[2][4];
            #pragma unroll
            for (int mt = 0; mt < 2; mt++) {
                int ar = warpM * 32 + mt * 16 + g;
                a[mt][0] = f2tf32(As[st][ar][kk + tg]);
                a[mt][1] = f2tf32(As[st][ar + 8][kk + tg]);
                a[mt][2] = f2tf32(As[st][ar][kk + tg + 4]);
                a[mt][3] = f2tf32(As[st][ar + 8][kk + tg + 4]);
            }
            #pragma unroll
            for (int nt = 0; nt < 8; nt++) {
                int bc = warpN * 64 + nt * 8 + g;
                unsigned b0 = f2tf32(Bs[st][kk + tg][bc]);
                unsigned bq = f2tf32(Bs[st][kk + tg + 4][bc]);
                #pragma unroll
                for (int mt = 0; mt < 2; mt++) {
                    asm volatile(
                        "mma.sync.aligned.m16n8k8.row.col.f32.tf32.tf32.f32 "
                        "{%0,%1,%2,%3}, {%4,%5,%6,%7}, {%8,%9}, {%0,%1,%2,%3};"
                        : "+f"(c[mt][nt][0]), "+f"(c[mt][nt][1]),
                          "+f"(c[mt][nt][2]), "+f"(c[mt][nt][3])
                        : "r"(a[mt][0]), "r"(a[mt][1]), "r"(a[mt][2]), "r"(a[mt][3]),
                          "r"(b0), "r"(bq));
                }
            }
        }
        __syncthreads();
    }

    __half2* Z2 = (__half2*)g_Z;
    #pragma unroll
    for (int mt = 0; mt < 2; mt++) {
        int row0 = blockM * 128 + warpM * 32 + mt * 16 + g;
        #pragma unroll
        for (int nt = 0; nt < 8; nt++) {
            int col = blockN * 128 + warpN * 64 + nt * 8 + 2 * tg;
            float bA = b1[col], bBv = b1[col + 1];
            Z2[((size_t)row0 * HH + col) >> 1] =
                __floats2half2_rn(c[mt][nt][0] + bA, c[mt][nt][1] + bBv);
            Z2[((size_t)(row0 + 8) * HH + col) >> 1] =
                __floats2half2_rn(c[mt][nt][2] + bA, c[mt][nt][3] + bBv);
        }
    }
}

// ---------------------------------------------------------------------------
// Pooling partial over one (b, 32-row tile), q in smem.
// ---------------------------------------------------------------------------
__device__ __forceinline__ void pool_tile(const float* qs,
                                          int b, int t, int tid,
                                          float4* red)
{
    const int lane = tid & 31;
    const int strp = tid >> 5;
    const int n0   = t * 32;

    float acc[8];
    #pragma unroll
    for (int i = 0; i < 8; i++) acc[i] = 0.f;

    #pragma unroll
    for (int r = 0; r < 4; r++) {
        int n = n0 + strp * 4 + r;
        float qv = qs[strp * 4 + r];
        const uint4 vz = *(const uint4*)(g_VH + (size_t)(b * NN + n) * DD + lane * 8);
        float2 v0 = __half22float2(*(__half2*)&vz.x);
        float2 v1 = __half22float2(*(__half2*)&vz.y);
        float2 v2 = __half22float2(*(__half2*)&vz.z);
        float2 v3 = __half22float2(*(__half2*)&vz.w);
        acc[0] += qv * v0.x; acc[1] += qv * v0.y;
        acc[2] += qv * v1.x; acc[3] += qv * v1.y;
        acc[4] += qv * v2.x; acc[5] += qv * v2.y;
        acc[6] += qv * v3.x; acc[7] += qv * v3.y;
    }
    red[strp * 64 + lane * 2]     = make_float4(acc[0], acc[1], acc[2], acc[3]);
    red[strp * 64 + lane * 2 + 1] = make_float4(acc[4], acc[5], acc[6], acc[7]);
    __syncthreads();
    if (tid < 64) {
        float4 s = red[tid];
        #pragma unroll
        for (int sx = 1; sx < 8; sx++) {
            float4 p = red[sx * 64 + tid];
            s.x += p.x; s.y += p.y; s.z += p.z; s.w += p.w;
        }
        ((float4*)g_part)[(b * NTILE + t) * (DD / 4) + tid] = s;
    }
}

// ---------------------------------------------------------------------------
// Kernel P0 (once): pooling partials from q_init.
// ---------------------------------------------------------------------------
__global__ __launch_bounds__(256) void pool0_kernel(const float* __restrict__ q)
{
    const int t = blockIdx.x, b = blockIdx.y, tid = threadIdx.x;
    __shared__ float qs[32];
    __shared__ float4 red[8 * 64];
    if (tid < 32) qs[tid] = q[b * NN + t * 32 + tid];
    __syncthreads();
    pool_tile(qs, b, t, tid, red);
}

// ---------------------------------------------------------------------------
// Kernel U (per iter): pooled = sum partials; u = pooled @ W1p.
// grid (BB, 2), 256 threads. 8 independent accumulators, full unroll -> MLP.
// ---------------------------------------------------------------------------
__global__ __launch_bounds__(256, 4) void u_kernel(
    const float* __restrict__ W1,
    float* __restrict__ u)
{
    const int b    = blockIdx.x;
    const int half = blockIdx.y;
    const int tid  = threadIdx.x;

    __shared__ float pooled_s[DD];

    float p = 0.f;
    #pragma unroll
    for (int s = 0; s < NTILE; s++)
        p += g_part[(b * NTILE + s) * DD + tid];
    pooled_s[tid] = p;
    __syncthreads();

    const int h = half * 256 + tid;
    const float* __restrict__ W1ph = W1 + (size_t)DD * HH + h;

    float a0 = 0.f, a1 = 0.f, a2 = 0.f, a3 = 0.f;
    float a4 = 0.f, a5 = 0.f, a6 = 0.f, a7 = 0.f;
    #pragma unroll
    for (int d = 0; d < DD; d += 8) {
        a0 += pooled_s[d + 0] * W1ph[(size_t)(d + 0) * HH];
        a1 += pooled_s[d + 1] * W1ph[(size_t)(d + 1) * HH];
        a2 += pooled_s[d + 2] * W1ph[(size_t)(d + 2) * HH];
        a3 += pooled_s[d + 3] * W1ph[(size_t)(d + 3) * HH];
        a4 += pooled_s[d + 4] * W1ph[(size_t)(d + 4) * HH];
        a5 += pooled_s[d + 5] * W1ph[(size_t)(d + 5) * HH];
        a6 += pooled_s[d + 6] * W1ph[(size_t)(d + 6) * HH];
        a7 += pooled_s[d + 7] * W1ph[(size_t)(d + 7) * HH];
    }
    u[b * HH + h] = ((a0 + a1) + (a2 + a3)) + ((a4 + a5) + (a6 + a7));
}

// ---------------------------------------------------------------------------
// Kernel S (per iter): fused score + pooling partial. POOL=false on last iter.
// ---------------------------------------------------------------------------
template <bool POOL>
__global__ __launch_bounds__(256) void score_pool_kernel(
    const float* __restrict__ u,
    const float* __restrict__ W2,
    const float* __restrict__ b2,
    float* __restrict__ qout)
{
    const int t   = blockIdx.x;     // 0..15
    const int b   = blockIdx.y;     // 0..63
    const int tid = threadIdx.x;
    const int w   = tid >> 5;
    const int l   = tid & 31;

    __shared__ float4 us4[HH / 4];
    __shared__ float4 w24[HH / 4];
    __shared__ float  qs[32];
    __shared__ float4 red[8 * 64];

    if (tid < HH / 4) {
        us4[tid] = ((const float4*)(u + b * HH))[tid];
        w24[tid] = ((const float4*)W2)[tid];
    }
    __syncthreads();

    const float b2v = b2[0];

    #pragma unroll
    for (int r = 0; r < 4; r++) {
        const int n = t * 32 + w * 4 + r;
        const uint4* __restrict__ z8 =
            (const uint4*)(g_Z + (size_t)(b * NN + n) * HH);
        float acc = 0.f;
        #pragma unroll
        for (int k = 0; k < 2; k++) {
            int idx = l + 32 * k;
            uint4 zr = z8[idx];
            float4 u0 = us4[idx * 2], u1 = us4[idx * 2 + 1];
            float4 w0 = w24[idx * 2], w1 = w24[idx * 2 + 1];
            float2 za = __half22float2(*(__half2*)&zr.x);
            float2 zb = __half22float2(*(__half2*)&zr.y);
            float2 zc = __half22float2(*(__half2*)&zr.z);
            float2 zd = __half22float2(*(__half2*)&zr.w);
            acc += fmaxf(za.x + u0.x, 0.f) * w0.x;
            acc += fmaxf(za.y + u0.y, 0.f) * w0.y;
            acc += fmaxf(zb.x + u0.z, 0.f) * w0.z;
            acc += fmaxf(zb.y + u0.w, 0.f) * w0.w;
            acc += fmaxf(zc.x + u1.x, 0.f) * w1.x;
            acc += fmaxf(zc.y + u1.y, 0.f) * w1.y;
            acc += fmaxf(zd.x + u1.z, 0.f) * w1.z;
            acc += fmaxf(zd.y + u1.w, 0.f) * w1.w;
        }
        #pragma unroll
        for (int off = 16; off; off >>= 1)
            acc += __shfl_xor_sync(0xffffffffu, acc, off);
        if (l == 0) {
            float qv = 1.f / (1.f + expf(-(acc + b2v)));
            if (POOL) qs[w * 4 + r] = qv;
            qout[b * NN + n] = qv;
        }
    }
    if (POOL) {
        __syncthreads();
        pool_tile(qs, b, t, tid, red);
    }
}

// ---------------------------------------------------------------------------
extern "C" void kernel_launch(void* const* d_in, const int* in_sizes, int n_in,
                              void* d_out, int out_size) {
    const float* q_init = (const float*)d_in[0];
    const float* V      = (const float*)d_in[1];
    const float* W1     = (const float*)d_in[2];
    const float* b1     = (const float*)d_in[3];
    const float* W2     = (const float*)d_in[4];
    const float* b2     = (const float*)d_in[5];
    float* out = (float*)d_out;

    float* g_q_p;
    float* g_u_p;
    cudaGetSymbolAddress((void**)&g_q_p, g_q);
    cudaGetSymbolAddress((void**)&g_u_p, g_u);

    convert_v_kernel<<<4096, 256>>>(V);
    zgemm_kernel<<<dim3(4, 256), 256>>>(V, W1, b1);
    pool0_kernel<<<dim3(NTILE, BB), 256>>>(q_init);

    for (int it = 0; it < MAX_ITER; it++) {
        u_kernel<<<dim3(BB, 2), 256>>>(W1, g_u_p);
        if (it == MAX_ITER - 1) {
            score_pool_kernel<false><<<dim3(NTILE, BB), 256>>>(g_u_p, W2, b2, out);
        } else {
            score_pool_kernel<true><<<dim3(NTILE, BB), 256>>>(g_u_p, W2, b2, g_q_p);
        }
    }
}